// round 14
// baseline (speedup 1.0000x reference)
#include <cuda_runtime.h>
#include <cuda_fp16.h>
#include <cstdint>

// Problem constants
#define DIMC   512
#define HEADS  8
#define WIN    128
#define HD     64
#define NTOK   65536          // 16*4096
#define NWIN   512            // NTOK/WIN
#define BH     (NWIN*HEADS)   // 4096

// Scratch (device globals)
__device__ __half hx[(size_t)NTOK * DIMC];        // fp16 copy of x
__device__ __half hwqkv[(size_t)3 * DIMC * DIMC]; // fp16 w_qkv
__device__ __half hwproj[(size_t)DIMC * DIMC];    // fp16 w_proj
__device__ __half g_qh[(size_t)BH * WIN * HD];    // fp16 q [win,h,t,d]
__device__ __half g_kh[(size_t)BH * WIN * HD];
__device__ __half g_vh[(size_t)BH * WIN * HD];
__device__ __half g_oh[(size_t)NTOK * DIMC];      // fp16 attention output

// ---------------------------------------------------------------------------
// helpers
// ---------------------------------------------------------------------------
__device__ __forceinline__ uint32_t s2u(const void* p) {
    uint32_t a;
    asm("{ .reg .u64 t; cvta.to.shared.u64 t, %1; cvt.u32.u64 %0, t; }"
        : "=r"(a) : "l"(p));
    return a;
}

__device__ __forceinline__ void cp16(uint32_t dst, const void* src) {
    asm volatile("cp.async.cg.shared.global [%0], [%1], 16;" :: "r"(dst), "l"(src));
}
#define CP_COMMIT() asm volatile("cp.async.commit_group;" ::: "memory")

__device__ __forceinline__ void ldsm_x4(uint32_t* r, uint32_t a) {
    asm volatile("ldmatrix.sync.aligned.m8n8.x4.shared.b16 {%0,%1,%2,%3}, [%4];"
        : "=r"(r[0]), "=r"(r[1]), "=r"(r[2]), "=r"(r[3]) : "r"(a));
}

__device__ __forceinline__ void ldsm_x4t(uint32_t* r, uint32_t a) {
    asm volatile("ldmatrix.sync.aligned.m8n8.x4.trans.shared.b16 {%0,%1,%2,%3}, [%4];"
        : "=r"(r[0]), "=r"(r[1]), "=r"(r[2]), "=r"(r[3]) : "r"(a));
}

__device__ __forceinline__ void mma_f16(float* d, const uint32_t* a,
                                        const uint32_t b0, const uint32_t b1) {
    asm volatile(
        "mma.sync.aligned.m16n8k16.row.col.f32.f16.f16.f32 "
        "{%0,%1,%2,%3}, {%4,%5,%6,%7}, {%8,%9}, {%0,%1,%2,%3};"
        : "+f"(d[0]), "+f"(d[1]), "+f"(d[2]), "+f"(d[3])
        : "r"(a[0]), "r"(a[1]), "r"(a[2]), "r"(a[3]), "r"(b0), "r"(b1));
}

__device__ __forceinline__ uint32_t packh2(float x, float y) {
    __half2 h = __floats2half2_rn(x, y);
    return *(uint32_t*)&h;
}

// ---------------------------------------------------------------------------
// merged fp32 -> fp16 conversion for x, w_qkv, w_proj (one launch)
// ---------------------------------------------------------------------------
#define N4_X   (NTOK * DIMC / 4)             // 8388608
#define N4_WQ  (3 * DIMC * DIMC / 4)         // 196608
#define N4_WP  (DIMC * DIMC / 4)             // 65536
#define N4_ALL (N4_X + N4_WQ + N4_WP)

__global__ void cvt_all(const float* __restrict__ x,
                        const float* __restrict__ wq,
                        const float* __restrict__ wp)
{
    int i = blockIdx.x * blockDim.x + threadIdx.x;
    if (i >= N4_ALL) return;
    const float* src;
    __half* dst;
    int j;
    if (i < N4_X)              { src = x;  dst = hx;     j = i; }
    else if (i < N4_X + N4_WQ) { src = wq; dst = hwqkv;  j = i - N4_X; }
    else                       { src = wp; dst = hwproj; j = i - N4_X - N4_WQ; }
    float4 v = ((const float4*)src)[j];
    ((__half2*)dst)[2 * j]     = __floats2half2_rn(v.x, v.y);
    ((__half2*)dst)[2 * j + 1] = __floats2half2_rn(v.z, v.w);
}

// ---------------------------------------------------------------------------
// fp16 HMMA GEMM, high-occupancy variant: block tile 64x128, BK=64, 2-stage
// cp.async, 256 threads / 8 warps, warp tile 32x32, 3 CTAs/SM (55.3 KB smem,
// <=85 regs). Three independent barrier domains per SM cover each other's
// pipeline bubbles.
// MODE 0: A=hx, B=hwqkv -> fp16 scatter into g_qh/g_kh/g_vh [win,h,t,d]
// MODE 1: A=g_oh, B=hwproj, +bias -> fp32 C
// ---------------------------------------------------------------------------
#define A_STG 9216                           // 64 rows * 144 B
#define B_STG 18432                          // 128 rows * 144 B
#define STG   (A_STG + B_STG)                // 27648 per stage
#define GEMM_SMEM (2 * STG)                  // 55296

template<int MODE>
__global__ void __launch_bounds__(256, 3)
hgemm(float* __restrict__ C, const float* __restrict__ bias)
{
    extern __shared__ __align__(128) char smem[];
    const __half* Ag = (MODE == 0) ? hx : g_oh;
    const __half* Bg = (MODE == 0) ? hwqkv : hwproj;

    const uint32_t sb = s2u(smem);
    const int tid  = threadIdx.x;
    const int m0   = blockIdx.y * 64;
    const int n0   = blockIdx.x * 128;
    const int warp = tid >> 5, lane = tid & 31;
    const int wy   = warp >> 2, wx = warp & 3;   // warp tile: (wy*32, wx*32)

    float acc[8][4];                             // [mt*4+nt]
#pragma unroll
    for (int i = 0; i < 8; ++i)
#pragma unroll
        for (int j = 0; j < 4; ++j) acc[i][j] = 0.0f;

    const int lrow = tid >> 3;                   // 0..31
    const int lc   = tid & 7;

    const uint32_t a_off0 = (wy * 32 +      (lane & 15)) * 144;
    const uint32_t a_off1 = (wy * 32 + 16 + (lane & 15)) * 144;
    const uint32_t colb   = ((lane >> 4) << 3) * 2;      // 0 or 16 bytes
    uint32_t b_off[2];
#pragma unroll
    for (int np = 0; np < 2; ++np)
        b_off[np] = (uint32_t)(wx * 32 + np * 16 + (lane & 7) +
                               ((lane >> 3) & 1) * 8) * 144;

    // stage loader: A 512 chunks (2/thread), B 1024 chunks (4/thread)
#define LOAD_STAGE(kt, s)                                                      \
    do {                                                                       \
        const uint32_t sa_  = sb + (s) * STG;                                  \
        const uint32_t sb2_ = sa_ + A_STG;                                     \
        _Pragma("unroll")                                                      \
        for (int u = 0; u < 2; ++u) {                                          \
            const int row = lrow + u * 32;                                     \
            cp16(sa_ + row * 144 + lc * 16,                                    \
                 Ag + (size_t)(m0 + row) * 512 + (kt) * 64 + lc * 8);          \
        }                                                                      \
        _Pragma("unroll")                                                      \
        for (int u = 0; u < 4; ++u) {                                          \
            const int row = lrow + u * 32;                                     \
            cp16(sb2_ + row * 144 + lc * 16,                                   \
                 Bg + (size_t)(n0 + row) * 512 + (kt) * 64 + lc * 8);          \
        }                                                                      \
        CP_COMMIT();                                                           \
    } while (0)

    LOAD_STAGE(0, 0);
    LOAD_STAGE(1, 1);

#pragma unroll
    for (int kt = 0; kt < 8; ++kt) {
        if (kt == 7)
            asm volatile("cp.async.wait_group 0;" ::: "memory");
        else
            asm volatile("cp.async.wait_group 1;" ::: "memory");
        __syncthreads();

        const uint32_t sa_  = sb + (kt & 1) * STG;
        const uint32_t sb2_ = sa_ + A_STG;

#pragma unroll
        for (int ks = 0; ks < 4; ++ks) {
            const uint32_t cb_ = ks * 32 + colb;
            uint32_t af[2][4], bf[2][4];
            ldsm_x4(af[0], sa_ + a_off0 + cb_);
            ldsm_x4(af[1], sa_ + a_off1 + cb_);
            ldsm_x4(bf[0], sb2_ + b_off[0] + cb_);
            ldsm_x4(bf[1], sb2_ + b_off[1] + cb_);
#pragma unroll
            for (int mt = 0; mt < 2; ++mt)
#pragma unroll
                for (int nt = 0; nt < 4; ++nt)
                    mma_f16(acc[mt * 4 + nt], af[mt],
                            bf[nt >> 1][nt & 1], bf[nt >> 1][(nt & 1) + 2]);
        }

        __syncthreads();                         // all reads of stage done
        if (kt + 2 < 8) LOAD_STAGE(kt + 2, kt & 1);
    }
#undef LOAD_STAGE

    // epilogue
#pragma unroll
    for (int mt = 0; mt < 2; ++mt) {
#pragma unroll
        for (int nt = 0; nt < 4; ++nt) {
            const int m = m0 + wy * 32 + mt * 16 + (lane >> 2);
            const int n = n0 + wx * 32 + nt * 8 + ((lane & 3) << 1);
            const float* a = acc[mt * 4 + nt];
            if (MODE == 0) {
                const int sidx = n >> 9;
                const int h    = (n >> 6) & 7;
                const int d    = n & 63;
                __half* dst = (sidx == 0) ? g_qh : ((sidx == 1) ? g_kh : g_vh);
                const int win = m >> 7;
                const size_t b0i =
                    (((size_t)(win * HEADS + h)) * WIN + (m & 127)) * HD + d;
                const size_t b1i =
                    (((size_t)(win * HEADS + h)) * WIN + ((m + 8) & 127)) * HD + d;
                *(uint32_t*)&dst[b0i] = packh2(a[0], a[1]);
                *(uint32_t*)&dst[b1i] = packh2(a[2], a[3]);
            } else {
                const float2 bv = *(const float2*)&bias[n];
                *(float2*)&C[(size_t)m * 512 + n] =
                    make_float2(a[0] + bv.x, a[1] + bv.y);
                *(float2*)&C[(size_t)(m + 8) * 512 + n] =
                    make_float2(a[2] + bv.x, a[3] + bv.y);
            }
        }
    }
}

// ---------------------------------------------------------------------------
// HMMA attention with causal block skipping: one CTA per (window, head),
// 256 threads / 8 warps. (unchanged, proven)
// ---------------------------------------------------------------------------
#define APAD 144                             // bytes per smem row (72 halfs)
#define ATILE (128 * APAD)                   // 18432
#define ATTN_SMEM (3 * ATILE)                // 55296

__global__ void __launch_bounds__(256, 2)
attn_tc()
{
    extern __shared__ __align__(128) char smem[];
    const uint32_t sQ = s2u(smem);
    const uint32_t sK = sQ + ATILE;
    const uint32_t sV = sK + ATILE;

    const int bh   = blockIdx.x;
    const int tid  = threadIdx.x;
    const int warp = tid >> 5, lane = tid & 31;

    const __half* qg = g_qh + (size_t)bh * (WIN * HD);
    const __half* kg = g_kh + (size_t)bh * (WIN * HD);
    const __half* vg = g_vh + (size_t)bh * (WIN * HD);

#pragma unroll
    for (int u = 0; u < 4; ++u) {
        const int id  = tid + u * 256;
        const int row = id >> 3, c = id & 7;
        const uint32_t off = row * APAD + c * 16;
        cp16(sQ + off, qg + row * 64 + c * 8);
        cp16(sK + off, kg + row * 64 + c * 8);
        cp16(sV + off, vg + row * 64 + c * 8);
    }
    CP_COMMIT();
    asm volatile("cp.async.wait_group 0;" ::: "memory");
    __syncthreads();

    // ---- S = Q K^T : per warp 16 x 128; skip np > warp ----
    float sacc[16][4];
#pragma unroll
    for (int i = 0; i < 16; ++i)
#pragma unroll
        for (int j = 0; j < 4; ++j) sacc[i][j] = 0.0f;

#pragma unroll
    for (int ks = 0; ks < 4; ++ks) {
        const int col = ks * 16 + ((lane >> 4) << 3);
        uint32_t af[4];
        {
            const int row = warp * 16 + (lane & 15);
            ldsm_x4(af, sQ + row * APAD + col * 2);
        }
#pragma unroll
        for (int np = 0; np < 8; ++np) {
            if (np <= warp) {
                uint32_t bf[4];
                const int row = np * 16 + (lane & 7) + ((lane >> 3) & 1) * 8;
                ldsm_x4(bf, sK + row * APAD + col * 2);
                mma_f16(sacc[np * 2 + 0], af, bf[0], bf[2]);
                mma_f16(sacc[np * 2 + 1], af, bf[1], bf[3]);
            }
        }
    }

    // ---- causal mask + softmax in registers ----
    const int rlo = warp * 16 + (lane >> 2);
    const int rhi = rlo + 8;
    float mx0 = -1e30f, mx1 = -1e30f;
#pragma unroll
    for (int nt = 0; nt < 16; ++nt) {
        if (nt <= 2 * warp + 1) {
            const int cb = nt * 8 + ((lane & 3) << 1);
            float s0 = sacc[nt][0] * 0.125f;
            float s1 = sacc[nt][1] * 0.125f;
            float s2 = sacc[nt][2] * 0.125f;
            float s3 = sacc[nt][3] * 0.125f;
            if (cb     > rlo) s0 = -1e30f;
            if (cb + 1 > rlo) s1 = -1e30f;
            if (cb     > rhi) s2 = -1e30f;
            if (cb + 1 > rhi) s3 = -1e30f;
            sacc[nt][0] = s0; sacc[nt][1] = s1;
            sacc[nt][2] = s2; sacc[nt][3] = s3;
            mx0 = fmaxf(mx0, fmaxf(s0, s1));
            mx1 = fmaxf(mx1, fmaxf(s2, s3));
        }
    }
    mx0 = fmaxf(mx0, __shfl_xor_sync(0xffffffffu, mx0, 1));
    mx0 = fmaxf(mx0, __shfl_xor_sync(0xffffffffu, mx0, 2));
    mx1 = fmaxf(mx1, __shfl_xor_sync(0xffffffffu, mx1, 1));
    mx1 = fmaxf(mx1, __shfl_xor_sync(0xffffffffu, mx1, 2));

    float sum0 = 0.0f, sum1 = 0.0f;
#pragma unroll
    for (int nt = 0; nt < 16; ++nt) {
        if (nt <= 2 * warp + 1) {
            float e0 = __expf(sacc[nt][0] - mx0);
            float e1 = __expf(sacc[nt][1] - mx0);
            float e2 = __expf(sacc[nt][2] - mx1);
            float e3 = __expf(sacc[nt][3] - mx1);
            sacc[nt][0] = e0; sacc[nt][1] = e1;
            sacc[nt][2] = e2; sacc[nt][3] = e3;
            sum0 += e0 + e1;
            sum1 += e2 + e3;
        }
    }
    sum0 += __shfl_xor_sync(0xffffffffu, sum0, 1);
    sum0 += __shfl_xor_sync(0xffffffffu, sum0, 2);
    sum1 += __shfl_xor_sync(0xffffffffu, sum1, 1);
    sum1 += __shfl_xor_sync(0xffffffffu, sum1, 2);
    const float inv0 = 1.0f / sum0;
    const float inv1 = 1.0f / sum1;

    // ---- O = P V : per warp 16 x 64; skip kt > warp ----
    float oacc[8][4];
#pragma unroll
    for (int i = 0; i < 8; ++i)
#pragma unroll
        for (int j = 0; j < 4; ++j) oacc[i][j] = 0.0f;

#pragma unroll
    for (int kt = 0; kt < 8; ++kt) {
        if (kt <= warp) {
            uint32_t ap[4];
            ap[0] = packh2(sacc[2 * kt][0] * inv0,     sacc[2 * kt][1] * inv0);
            ap[1] = packh2(sacc[2 * kt][2] * inv1,     sacc[2 * kt][3] * inv1);
            ap[2] = packh2(sacc[2 * kt + 1][0] * inv0, sacc[2 * kt + 1][1] * inv0);
            ap[3] = packh2(sacc[2 * kt + 1][2] * inv1, sacc[2 * kt + 1][3] * inv1);

#pragma unroll
            for (int nb = 0; nb < 4; ++nb) {
                uint32_t bv[4];
                const int row = kt * 16 + (lane & 15);
                const int col = nb * 16 + ((lane >> 4) << 3);
                ldsm_x4t(bv, sV + row * APAD + col * 2);
                mma_f16(oacc[nb * 2 + 0], ap, bv[0], bv[1]);
                mma_f16(oacc[nb * 2 + 1], ap, bv[2], bv[3]);
            }
        }
    }

    // ---- write O to g_oh [token][C] fp16 ----
    const int win = bh >> 3, h = bh & 7;
    const size_t row_lo = (size_t)(win * WIN + warp * 16 + (lane >> 2)) * DIMC
                          + h * HD + ((lane & 3) << 1);
#pragma unroll
    for (int nt = 0; nt < 8; ++nt) {
        *(uint32_t*)&g_oh[row_lo + nt * 8]            = packh2(oacc[nt][0], oacc[nt][1]);
        *(uint32_t*)&g_oh[row_lo + 8 * DIMC + nt * 8] = packh2(oacc[nt][2], oacc[nt][3]);
    }
}

// ---------------------------------------------------------------------------
extern "C" void kernel_launch(void* const* d_in, const int* in_sizes, int n_in,
                              void* d_out, int out_size)
{
    const float* x      = (const float*)d_in[0];  // [16,4096,512]
    const float* w_qkv  = (const float*)d_in[1];  // [1536,512]
    const float* w_proj = (const float*)d_in[2];  // [512,512]
    const float* b_proj = (const float*)d_in[3];  // [512]
    float* out = (float*)d_out;                   // [16,4096,512]

    cudaFuncSetAttribute(hgemm<0>, cudaFuncAttributeMaxDynamicSharedMemorySize,
                         GEMM_SMEM);
    cudaFuncSetAttribute(hgemm<1>, cudaFuncAttributeMaxDynamicSharedMemorySize,
                         GEMM_SMEM);
    cudaFuncSetAttribute(hgemm<0>,
                         cudaFuncAttributePreferredSharedMemoryCarveout, 100);
    cudaFuncSetAttribute(hgemm<1>,
                         cudaFuncAttributePreferredSharedMemoryCarveout, 100);
    cudaFuncSetAttribute(attn_tc, cudaFuncAttributeMaxDynamicSharedMemorySize,
                         ATTN_SMEM);
    cudaFuncSetAttribute(attn_tc,
                         cudaFuncAttributePreferredSharedMemoryCarveout, 100);

    // 0) fp32 -> fp16 conversions (single launch)
    cvt_all<<<(N4_ALL + 255) / 256, 256>>>(x, w_qkv, w_proj);

    // 1) fused QKV projection -> fp16 g_qh/g_kh/g_vh
    dim3 g1(1536 / 128, NTOK / 64);
    hgemm<0><<<g1, 256, GEMM_SMEM>>>(nullptr, nullptr);

    // 2) HMMA attention (causal block skipping) -> fp16 g_oh
    attn_tc<<<BH, 256, ATTN_SMEM>>>();

    // 3) output projection + bias -> fp32 d_out
    dim3 g2(512 / 128, NTOK / 64);
    hgemm<1><<<g2, 256, GEMM_SMEM>>>(out, b_proj);
}

// round 15
// speedup vs baseline: 1.1005x; 1.1005x over previous
#include <cuda_runtime.h>
#include <cuda_fp16.h>
#include <cstdint>

// Problem constants
#define DIMC   512
#define HEADS  8
#define WIN    128
#define HD     64
#define NTOK   65536          // 16*4096
#define NWIN   512            // NTOK/WIN
#define BH     (NWIN*HEADS)   // 4096

// Scratch (device globals)
__device__ __half hx[(size_t)NTOK * DIMC];        // fp16 copy of x
__device__ __half hwqkv[(size_t)3 * DIMC * DIMC]; // fp16 w_qkv
__device__ __half hwproj[(size_t)DIMC * DIMC];    // fp16 w_proj
__device__ __half g_qh[(size_t)BH * WIN * HD];    // fp16 q [win,h,t,d]
__device__ __half g_kh[(size_t)BH * WIN * HD];
__device__ __half g_vh[(size_t)BH * WIN * HD];
__device__ __half g_oh[(size_t)NTOK * DIMC];      // fp16 attention output

// ---------------------------------------------------------------------------
// helpers
// ---------------------------------------------------------------------------
__device__ __forceinline__ uint32_t s2u(const void* p) {
    uint32_t a;
    asm("{ .reg .u64 t; cvta.to.shared.u64 t, %1; cvt.u32.u64 %0, t; }"
        : "=r"(a) : "l"(p));
    return a;
}

__device__ __forceinline__ void cp16(uint32_t dst, const void* src) {
    asm volatile("cp.async.cg.shared.global [%0], [%1], 16;" :: "r"(dst), "l"(src));
}
#define CP_COMMIT() asm volatile("cp.async.commit_group;" ::: "memory")

__device__ __forceinline__ void ldsm_x4(uint32_t* r, uint32_t a) {
    asm volatile("ldmatrix.sync.aligned.m8n8.x4.shared.b16 {%0,%1,%2,%3}, [%4];"
        : "=r"(r[0]), "=r"(r[1]), "=r"(r[2]), "=r"(r[3]) : "r"(a));
}

__device__ __forceinline__ void ldsm_x4t(uint32_t* r, uint32_t a) {
    asm volatile("ldmatrix.sync.aligned.m8n8.x4.trans.shared.b16 {%0,%1,%2,%3}, [%4];"
        : "=r"(r[0]), "=r"(r[1]), "=r"(r[2]), "=r"(r[3]) : "r"(a));
}

__device__ __forceinline__ void mma_f16(float* d, const uint32_t* a,
                                        const uint32_t b0, const uint32_t b1) {
    asm volatile(
        "mma.sync.aligned.m16n8k16.row.col.f32.f16.f16.f32 "
        "{%0,%1,%2,%3}, {%4,%5,%6,%7}, {%8,%9}, {%0,%1,%2,%3};"
        : "+f"(d[0]), "+f"(d[1]), "+f"(d[2]), "+f"(d[3])
        : "r"(a[0]), "r"(a[1]), "r"(a[2]), "r"(a[3]), "r"(b0), "r"(b1));
}

__device__ __forceinline__ uint32_t packh2(float x, float y) {
    __half2 h = __floats2half2_rn(x, y);
    return *(uint32_t*)&h;
}

// ---------------------------------------------------------------------------
// merged fp32 -> fp16 conversion for x, w_qkv, w_proj (one launch)
// ---------------------------------------------------------------------------
#define N4_X   (NTOK * DIMC / 4)             // 8388608
#define N4_WQ  (3 * DIMC * DIMC / 4)         // 196608
#define N4_WP  (DIMC * DIMC / 4)             // 65536
#define N4_ALL (N4_X + N4_WQ + N4_WP)

__global__ void cvt_all(const float* __restrict__ x,
                        const float* __restrict__ wq,
                        const float* __restrict__ wp)
{
    int i = blockIdx.x * blockDim.x + threadIdx.x;
    if (i >= N4_ALL) return;
    const float* src;
    __half* dst;
    int j;
    if (i < N4_X)              { src = x;  dst = hx;     j = i; }
    else if (i < N4_X + N4_WQ) { src = wq; dst = hwqkv;  j = i - N4_X; }
    else                       { src = wp; dst = hwproj; j = i - N4_X - N4_WQ; }
    float4 v = ((const float4*)src)[j];
    ((__half2*)dst)[2 * j]     = __floats2half2_rn(v.x, v.y);
    ((__half2*)dst)[2 * j + 1] = __floats2half2_rn(v.z, v.w);
}

// ---------------------------------------------------------------------------
// fp16 HMMA GEMM (R10 configuration — proven best): block tile 128x128,
// BK=64, 3-stage cp.async, 256 threads / 8 warps, warp tile 32x64, 2 CTAs/SM,
// fragment software pipelining (ldmatrix for ks+1 before MMAs of ks).
// MODE 0: A=hx, B=hwqkv -> fp16 scatter into g_qh/g_kh/g_vh [win,h,t,d]
// MODE 1: A=g_oh, B=hwproj, +bias -> fp32 C
// ---------------------------------------------------------------------------
#define T_STG 18432                          // 128 rows * 144 B (one matrix)
#define STG   (2 * T_STG)                    // 36864 per stage
#define GEMM_SMEM (3 * STG)                  // 110592

template<int MODE>
__global__ void __launch_bounds__(256, 2)
hgemm(float* __restrict__ C, const float* __restrict__ bias)
{
    extern __shared__ __align__(128) char smem[];
    const __half* Ag = (MODE == 0) ? hx : g_oh;
    const __half* Bg = (MODE == 0) ? hwqkv : hwproj;

    const uint32_t sb = s2u(smem);
    const int tid  = threadIdx.x;
    const int m0   = blockIdx.y * 128;
    const int n0   = blockIdx.x * 128;
    const int warp = tid >> 5, lane = tid & 31;
    const int wy   = warp >> 1, wx = warp & 1;   // warp tile: (wy*32, wx*64)

    float acc[16][4];
#pragma unroll
    for (int i = 0; i < 16; ++i)
#pragma unroll
        for (int j = 0; j < 4; ++j) acc[i][j] = 0.0f;

    const int lrow = tid >> 3;                   // 0..31
    const int lc   = tid & 7;

    const uint32_t a_off0 = (wy * 32 +      (lane & 15)) * 144;
    const uint32_t a_off1 = (wy * 32 + 16 + (lane & 15)) * 144;
    const uint32_t colb   = ((lane >> 4) << 3) * 2;      // 0 or 16 bytes
    uint32_t b_off[4];
#pragma unroll
    for (int np = 0; np < 4; ++np)
        b_off[np] = (uint32_t)(wx * 64 + np * 16 + (lane & 7) +
                               ((lane >> 3) & 1) * 8) * 144;

#define LOAD_STAGE(kt, s)                                                      \
    do {                                                                       \
        const uint32_t sa_  = sb + (s) * STG;                                  \
        const uint32_t sb2_ = sa_ + T_STG;                                     \
        _Pragma("unroll")                                                      \
        for (int u = 0; u < 4; ++u) {                                          \
            const int row = lrow + u * 32;                                     \
            cp16(sa_ + row * 144 + lc * 16,                                    \
                 Ag + (size_t)(m0 + row) * 512 + (kt) * 64 + lc * 8);          \
            cp16(sb2_ + row * 144 + lc * 16,                                   \
                 Bg + (size_t)(n0 + row) * 512 + (kt) * 64 + lc * 8);          \
        }                                                                      \
        CP_COMMIT();                                                           \
    } while (0)

#define LDSM_KS(ks, bi, saq, sbq)                                              \
    do {                                                                       \
        const uint32_t cb_ = (ks) * 32 + colb;                                 \
        ldsm_x4(af[bi][0], (saq) + a_off0 + cb_);                              \
        ldsm_x4(af[bi][1], (saq) + a_off1 + cb_);                              \
        ldsm_x4(bf[bi][0], (sbq) + b_off[0] + cb_);                            \
        ldsm_x4(bf[bi][1], (sbq) + b_off[1] + cb_);                            \
        ldsm_x4(bf[bi][2], (sbq) + b_off[2] + cb_);                            \
        ldsm_x4(bf[bi][3], (sbq) + b_off[3] + cb_);                            \
    } while (0)

#define MMA_KS(bi)                                                             \
    do {                                                                       \
        _Pragma("unroll")                                                      \
        for (int mt = 0; mt < 2; ++mt)                                         \
            _Pragma("unroll")                                                  \
            for (int nt = 0; nt < 8; ++nt)                                     \
                mma_f16(acc[mt * 8 + nt], af[bi][mt],                          \
                        bf[bi][nt >> 1][nt & 1], bf[bi][nt >> 1][(nt & 1) + 2]);\
    } while (0)

    LOAD_STAGE(0, 0);
    LOAD_STAGE(1, 1);

    uint32_t af[2][2][4], bf[2][4][4];

#pragma unroll
    for (int kt = 0; kt < 8; ++kt) {
        if (kt == 7)
            asm volatile("cp.async.wait_group 0;" ::: "memory");
        else
            asm volatile("cp.async.wait_group 1;" ::: "memory");
        __syncthreads();

        if (kt + 2 < 8) LOAD_STAGE(kt + 2, (kt + 2) % 3);

        const uint32_t sa_  = sb + (kt % 3) * STG;
        const uint32_t sb2_ = sa_ + T_STG;

        LDSM_KS(0, 0, sa_, sb2_);
#pragma unroll
        for (int ks = 0; ks < 4; ++ks) {
            const int cur = ks & 1, nxt = cur ^ 1;
            if (ks < 3) LDSM_KS(ks + 1, nxt, sa_, sb2_);
            MMA_KS(cur);
        }
    }
#undef LOAD_STAGE
#undef LDSM_KS
#undef MMA_KS

    // epilogue
#pragma unroll
    for (int mt = 0; mt < 2; ++mt) {
#pragma unroll
        for (int nt = 0; nt < 8; ++nt) {
            const int m = m0 + wy * 32 + mt * 16 + (lane >> 2);
            const int n = n0 + wx * 64 + nt * 8 + ((lane & 3) << 1);
            const float* a = acc[mt * 8 + nt];
            if (MODE == 0) {
                const int sidx = n >> 9;
                const int h    = (n >> 6) & 7;
                const int d    = n & 63;
                __half* dst = (sidx == 0) ? g_qh : ((sidx == 1) ? g_kh : g_vh);
                const int win = m >> 7;
                const size_t b0i =
                    (((size_t)(win * HEADS + h)) * WIN + (m & 127)) * HD + d;
                const size_t b1i = b0i + 8 * HD;
                *(uint32_t*)&dst[b0i] = packh2(a[0], a[1]);
                *(uint32_t*)&dst[b1i] = packh2(a[2], a[3]);
            } else {
                const float2 bv = *(const float2*)&bias[n];
                *(float2*)&C[(size_t)m * 512 + n] =
                    make_float2(a[0] + bv.x, a[1] + bv.y);
                *(float2*)&C[(size_t)(m + 8) * 512 + n] =
                    make_float2(a[2] + bv.x, a[3] + bv.y);
            }
        }
    }
}

// ---------------------------------------------------------------------------
// HMMA attention with causal block skipping (R10) + coalesced O writeback:
// O is staged into the sV smem region (free after P*V) and flushed with
// 128B-coalesced STG.128 rows instead of scattered 4B-pair stores.
// One CTA per (window, head), 256 threads / 8 warps.
// ---------------------------------------------------------------------------
#define APAD 144                             // bytes per smem row (72 halfs)
#define ATILE (128 * APAD)                   // 18432
#define ATTN_SMEM (3 * ATILE)                // 55296

__global__ void __launch_bounds__(256, 2)
attn_tc()
{
    extern __shared__ __align__(128) char smem[];
    const uint32_t sQ = s2u(smem);
    const uint32_t sK = sQ + ATILE;
    const uint32_t sV = sK + ATILE;

    const int bh   = blockIdx.x;
    const int tid  = threadIdx.x;
    const int warp = tid >> 5, lane = tid & 31;

    const __half* qg = g_qh + (size_t)bh * (WIN * HD);
    const __half* kg = g_kh + (size_t)bh * (WIN * HD);
    const __half* vg = g_vh + (size_t)bh * (WIN * HD);

#pragma unroll
    for (int u = 0; u < 4; ++u) {
        const int id  = tid + u * 256;
        const int row = id >> 3, c = id & 7;
        const uint32_t off = row * APAD + c * 16;
        cp16(sQ + off, qg + row * 64 + c * 8);
        cp16(sK + off, kg + row * 64 + c * 8);
        cp16(sV + off, vg + row * 64 + c * 8);
    }
    CP_COMMIT();
    asm volatile("cp.async.wait_group 0;" ::: "memory");
    __syncthreads();

    // ---- S = Q K^T : per warp 16 x 128; skip np > warp ----
    float sacc[16][4];
#pragma unroll
    for (int i = 0; i < 16; ++i)
#pragma unroll
        for (int j = 0; j < 4; ++j) sacc[i][j] = 0.0f;

#pragma unroll
    for (int ks = 0; ks < 4; ++ks) {
        const int col = ks * 16 + ((lane >> 4) << 3);
        uint32_t af[4];
        {
            const int row = warp * 16 + (lane & 15);
            ldsm_x4(af, sQ + row * APAD + col * 2);
        }
#pragma unroll
        for (int np = 0; np < 8; ++np) {
            if (np <= warp) {
                uint32_t bf[4];
                const int row = np * 16 + (lane & 7) + ((lane >> 3) & 1) * 8;
                ldsm_x4(bf, sK + row * APAD + col * 2);
                mma_f16(sacc[np * 2 + 0], af, bf[0], bf[2]);
                mma_f16(sacc[np * 2 + 1], af, bf[1], bf[3]);
            }
        }
    }

    // ---- causal mask + softmax in registers ----
    const int rlo = warp * 16 + (lane >> 2);
    const int rhi = rlo + 8;
    float mx0 = -1e30f, mx1 = -1e30f;
#pragma unroll
    for (int nt = 0; nt < 16; ++nt) {
        if (nt <= 2 * warp + 1) {
            const int cb = nt * 8 + ((lane & 3) << 1);
            float s0 = sacc[nt][0] * 0.125f;
            float s1 = sacc[nt][1] * 0.125f;
            float s2 = sacc[nt][2] * 0.125f;
            float s3 = sacc[nt][3] * 0.125f;
            if (cb     > rlo) s0 = -1e30f;
            if (cb + 1 > rlo) s1 = -1e30f;
            if (cb     > rhi) s2 = -1e30f;
            if (cb + 1 > rhi) s3 = -1e30f;
            sacc[nt][0] = s0; sacc[nt][1] = s1;
            sacc[nt][2] = s2; sacc[nt][3] = s3;
            mx0 = fmaxf(mx0, fmaxf(s0, s1));
            mx1 = fmaxf(mx1, fmaxf(s2, s3));
        }
    }
    mx0 = fmaxf(mx0, __shfl_xor_sync(0xffffffffu, mx0, 1));
    mx0 = fmaxf(mx0, __shfl_xor_sync(0xffffffffu, mx0, 2));
    mx1 = fmaxf(mx1, __shfl_xor_sync(0xffffffffu, mx1, 1));
    mx1 = fmaxf(mx1, __shfl_xor_sync(0xffffffffu, mx1, 2));

    float sum0 = 0.0f, sum1 = 0.0f;
#pragma unroll
    for (int nt = 0; nt < 16; ++nt) {
        if (nt <= 2 * warp + 1) {
            float e0 = __expf(sacc[nt][0] - mx0);
            float e1 = __expf(sacc[nt][1] - mx0);
            float e2 = __expf(sacc[nt][2] - mx1);
            float e3 = __expf(sacc[nt][3] - mx1);
            sacc[nt][0] = e0; sacc[nt][1] = e1;
            sacc[nt][2] = e2; sacc[nt][3] = e3;
            sum0 += e0 + e1;
            sum1 += e2 + e3;
        }
    }
    sum0 += __shfl_xor_sync(0xffffffffu, sum0, 1);
    sum0 += __shfl_xor_sync(0xffffffffu, sum0, 2);
    sum1 += __shfl_xor_sync(0xffffffffu, sum1, 1);
    sum1 += __shfl_xor_sync(0xffffffffu, sum1, 2);
    const float inv0 = 1.0f / sum0;
    const float inv1 = 1.0f / sum1;

    // ---- O = P V : per warp 16 x 64; skip kt > warp ----
    float oacc[8][4];
#pragma unroll
    for (int i = 0; i < 8; ++i)
#pragma unroll
        for (int j = 0; j < 4; ++j) oacc[i][j] = 0.0f;

#pragma unroll
    for (int kt = 0; kt < 8; ++kt) {
        if (kt <= warp) {
            uint32_t ap[4];
            ap[0] = packh2(sacc[2 * kt][0] * inv0,     sacc[2 * kt][1] * inv0);
            ap[1] = packh2(sacc[2 * kt][2] * inv1,     sacc[2 * kt][3] * inv1);
            ap[2] = packh2(sacc[2 * kt + 1][0] * inv0, sacc[2 * kt + 1][1] * inv0);
            ap[3] = packh2(sacc[2 * kt + 1][2] * inv1, sacc[2 * kt + 1][3] * inv1);

#pragma unroll
            for (int nb = 0; nb < 4; ++nb) {
                uint32_t bv[4];
                const int row = kt * 16 + (lane & 15);
                const int col = nb * 16 + ((lane >> 4) << 3);
                ldsm_x4t(bv, sV + row * APAD + col * 2);
                mma_f16(oacc[nb * 2 + 0], ap, bv[0], bv[1]);
                mma_f16(oacc[nb * 2 + 1], ap, bv[2], bv[3]);
            }
        }
    }

    // ---- stage O into smem (sV region is free after the PV loop) ----
    __syncthreads();   // all warps done reading sV; critical path set by warp 7
    {
        const uint32_t orow0 = sV + (warp * 16 + (lane >> 2)) * APAD
                             + ((lane & 3) << 2);          // bytes: col*2
        const uint32_t orow1 = orow0 + 8 * APAD;
#pragma unroll
        for (int nt = 0; nt < 8; ++nt) {
            asm volatile("st.shared.b32 [%0], %1;"
                :: "r"(orow0 + nt * 16), "r"(packh2(oacc[nt][0], oacc[nt][1]))
                : "memory");
            asm volatile("st.shared.b32 [%0], %1;"
                :: "r"(orow1 + nt * 16), "r"(packh2(oacc[nt][2], oacc[nt][3]))
                : "memory");
        }
    }
    __syncthreads();

    // ---- coalesced flush: each row's 128 B written as 16B chunks by 8
    //      consecutive threads -> full 128B transactions ----
    const int win = bh >> 3, h = bh & 7;
#pragma unroll
    for (int u = 0; u < 4; ++u) {
        const int id  = tid + u * 256;
        const int row = id >> 3, c = id & 7;
        uint4 v;
        asm volatile("ld.shared.v4.b32 {%0,%1,%2,%3}, [%4];"
            : "=r"(v.x), "=r"(v.y), "=r"(v.z), "=r"(v.w)
            : "r"(sV + row * APAD + c * 16));
        *(uint4*)&g_oh[(size_t)(win * WIN + row) * DIMC + h * HD + c * 8] = v;
    }
}

// ---------------------------------------------------------------------------
extern "C" void kernel_launch(void* const* d_in, const int* in_sizes, int n_in,
                              void* d_out, int out_size)
{
    const float* x      = (const float*)d_in[0];  // [16,4096,512]
    const float* w_qkv  = (const float*)d_in[1];  // [1536,512]
    const float* w_proj = (const float*)d_in[2];  // [512,512]
    const float* b_proj = (const float*)d_in[3];  // [512]
    float* out = (float*)d_out;                   // [16,4096,512]

    cudaFuncSetAttribute(hgemm<0>, cudaFuncAttributeMaxDynamicSharedMemorySize,
                         GEMM_SMEM);
    cudaFuncSetAttribute(hgemm<1>, cudaFuncAttributeMaxDynamicSharedMemorySize,
                         GEMM_SMEM);
    cudaFuncSetAttribute(hgemm<0>,
                         cudaFuncAttributePreferredSharedMemoryCarveout, 100);
    cudaFuncSetAttribute(hgemm<1>,
                         cudaFuncAttributePreferredSharedMemoryCarveout, 100);
    cudaFuncSetAttribute(attn_tc, cudaFuncAttributeMaxDynamicSharedMemorySize,
                         ATTN_SMEM);
    cudaFuncSetAttribute(attn_tc,
                         cudaFuncAttributePreferredSharedMemoryCarveout, 100);

    // 0) fp32 -> fp16 conversions (single launch)
    cvt_all<<<(N4_ALL + 255) / 256, 256>>>(x, w_qkv, w_proj);

    // 1) fused QKV projection -> fp16 g_qh/g_kh/g_vh
    dim3 g1(1536 / 128, NTOK / 128);
    hgemm<0><<<g1, 256, GEMM_SMEM>>>(nullptr, nullptr);

    // 2) HMMA attention (causal block skipping, coalesced O) -> fp16 g_oh
    attn_tc<<<BH, 256, ATTN_SMEM>>>();

    // 3) output projection + bias -> fp32 d_out
    dim3 g2(512 / 128, NTOK / 128);
    hgemm<1><<<g2, 256, GEMM_SMEM>>>(out, b_proj);
}

// round 16
// speedup vs baseline: 1.1119x; 1.0104x over previous
#include <cuda_runtime.h>
#include <cuda_fp16.h>
#include <cstdint>

// Problem constants
#define DIMC   512
#define HEADS  8
#define WIN    128
#define HD     64
#define NTOK   65536          // 16*4096
#define NWIN   512            // NTOK/WIN
#define BH     (NWIN*HEADS)   // 4096

// Scratch (device globals)
__device__ __half hx[(size_t)NTOK * DIMC];        // fp16 copy of x
__device__ __half hwqkv[(size_t)3 * DIMC * DIMC]; // fp16 w_qkv
__device__ __half hwproj[(size_t)DIMC * DIMC];    // fp16 w_proj
__device__ __half g_qh[(size_t)BH * WIN * HD];    // fp16 q [win,h,t,d]
__device__ __half g_kh[(size_t)BH * WIN * HD];
__device__ __half g_vh[(size_t)BH * WIN * HD];
__device__ __half g_oh[(size_t)NTOK * DIMC];      // fp16 attention output

// ---------------------------------------------------------------------------
// helpers
// ---------------------------------------------------------------------------
__device__ __forceinline__ uint32_t s2u(const void* p) {
    uint32_t a;
    asm("{ .reg .u64 t; cvta.to.shared.u64 t, %1; cvt.u32.u64 %0, t; }"
        : "=r"(a) : "l"(p));
    return a;
}

__device__ __forceinline__ void cp16(uint32_t dst, const void* src) {
    asm volatile("cp.async.cg.shared.global [%0], [%1], 16;" :: "r"(dst), "l"(src));
}
#define CP_COMMIT() asm volatile("cp.async.commit_group;" ::: "memory")

__device__ __forceinline__ void ldsm_x4(uint32_t* r, uint32_t a) {
    asm volatile("ldmatrix.sync.aligned.m8n8.x4.shared.b16 {%0,%1,%2,%3}, [%4];"
        : "=r"(r[0]), "=r"(r[1]), "=r"(r[2]), "=r"(r[3]) : "r"(a));
}

__device__ __forceinline__ void ldsm_x4t(uint32_t* r, uint32_t a) {
    asm volatile("ldmatrix.sync.aligned.m8n8.x4.trans.shared.b16 {%0,%1,%2,%3}, [%4];"
        : "=r"(r[0]), "=r"(r[1]), "=r"(r[2]), "=r"(r[3]) : "r"(a));
}

__device__ __forceinline__ void mma_f16(float* d, const uint32_t* a,
                                        const uint32_t b0, const uint32_t b1) {
    asm volatile(
        "mma.sync.aligned.m16n8k16.row.col.f32.f16.f16.f32 "
        "{%0,%1,%2,%3}, {%4,%5,%6,%7}, {%8,%9}, {%0,%1,%2,%3};"
        : "+f"(d[0]), "+f"(d[1]), "+f"(d[2]), "+f"(d[3])
        : "r"(a[0]), "r"(a[1]), "r"(a[2]), "r"(a[3]), "r"(b0), "r"(b1));
}

__device__ __forceinline__ uint32_t packh2(float x, float y) {
    __half2 h = __floats2half2_rn(x, y);
    return *(uint32_t*)&h;
}

// ---------------------------------------------------------------------------
// merged fp32 -> fp16 conversion for x, w_qkv, w_proj (one launch)
// ---------------------------------------------------------------------------
#define N4_X   (NTOK * DIMC / 4)             // 8388608
#define N4_WQ  (3 * DIMC * DIMC / 4)         // 196608
#define N4_WP  (DIMC * DIMC / 4)             // 65536
#define N4_ALL (N4_X + N4_WQ + N4_WP)

__global__ void cvt_all(const float* __restrict__ x,
                        const float* __restrict__ wq,
                        const float* __restrict__ wp)
{
    int i = blockIdx.x * blockDim.x + threadIdx.x;
    if (i >= N4_ALL) return;
    const float* src;
    __half* dst;
    int j;
    if (i < N4_X)              { src = x;  dst = hx;     j = i; }
    else if (i < N4_X + N4_WQ) { src = wq; dst = hwqkv;  j = i - N4_X; }
    else                       { src = wp; dst = hwproj; j = i - N4_X - N4_WQ; }
    float4 v = ((const float4*)src)[j];
    ((__half2*)dst)[2 * j]     = __floats2half2_rn(v.x, v.y);
    ((__half2*)dst)[2 * j + 1] = __floats2half2_rn(v.z, v.w);
}

// ---------------------------------------------------------------------------
// fp16 HMMA GEMM (R10 configuration — proven best): block tile 128x128,
// BK=64, 3-stage cp.async, 256 threads / 8 warps, warp tile 32x64, 2 CTAs/SM,
// fragment software pipelining (ldmatrix for ks+1 before MMAs of ks).
// MODE 0: A=hx, B=hwqkv -> fp16 scatter into g_qh/g_kh/g_vh [win,h,t,d]
// MODE 1: A=g_oh, B=hwproj, +bias -> fp32 C
// ---------------------------------------------------------------------------
#define T_STG 18432                          // 128 rows * 144 B (one matrix)
#define STG   (2 * T_STG)                    // 36864 per stage
#define GEMM_SMEM (3 * STG)                  // 110592

template<int MODE>
__global__ void __launch_bounds__(256, 2)
hgemm(float* __restrict__ C, const float* __restrict__ bias)
{
    extern __shared__ __align__(128) char smem[];
    const __half* Ag = (MODE == 0) ? hx : g_oh;
    const __half* Bg = (MODE == 0) ? hwqkv : hwproj;

    const uint32_t sb = s2u(smem);
    const int tid  = threadIdx.x;
    const int m0   = blockIdx.y * 128;
    const int n0   = blockIdx.x * 128;
    const int warp = tid >> 5, lane = tid & 31;
    const int wy   = warp >> 1, wx = warp & 1;   // warp tile: (wy*32, wx*64)

    float acc[16][4];
#pragma unroll
    for (int i = 0; i < 16; ++i)
#pragma unroll
        for (int j = 0; j < 4; ++j) acc[i][j] = 0.0f;

    const int lrow = tid >> 3;                   // 0..31
    const int lc   = tid & 7;

    const uint32_t a_off0 = (wy * 32 +      (lane & 15)) * 144;
    const uint32_t a_off1 = (wy * 32 + 16 + (lane & 15)) * 144;
    const uint32_t colb   = ((lane >> 4) << 3) * 2;      // 0 or 16 bytes
    uint32_t b_off[4];
#pragma unroll
    for (int np = 0; np < 4; ++np)
        b_off[np] = (uint32_t)(wx * 64 + np * 16 + (lane & 7) +
                               ((lane >> 3) & 1) * 8) * 144;

#define LOAD_STAGE(kt, s)                                                      \
    do {                                                                       \
        const uint32_t sa_  = sb + (s) * STG;                                  \
        const uint32_t sb2_ = sa_ + T_STG;                                     \
        _Pragma("unroll")                                                      \
        for (int u = 0; u < 4; ++u) {                                          \
            const int row = lrow + u * 32;                                     \
            cp16(sa_ + row * 144 + lc * 16,                                    \
                 Ag + (size_t)(m0 + row) * 512 + (kt) * 64 + lc * 8);          \
            cp16(sb2_ + row * 144 + lc * 16,                                   \
                 Bg + (size_t)(n0 + row) * 512 + (kt) * 64 + lc * 8);          \
        }                                                                      \
        CP_COMMIT();                                                           \
    } while (0)

#define LDSM_KS(ks, bi, saq, sbq)                                              \
    do {                                                                       \
        const uint32_t cb_ = (ks) * 32 + colb;                                 \
        ldsm_x4(af[bi][0], (saq) + a_off0 + cb_);                              \
        ldsm_x4(af[bi][1], (saq) + a_off1 + cb_);                              \
        ldsm_x4(bf[bi][0], (sbq) + b_off[0] + cb_);                            \
        ldsm_x4(bf[bi][1], (sbq) + b_off[1] + cb_);                            \
        ldsm_x4(bf[bi][2], (sbq) + b_off[2] + cb_);                            \
        ldsm_x4(bf[bi][3], (sbq) + b_off[3] + cb_);                            \
    } while (0)

#define MMA_KS(bi)                                                             \
    do {                                                                       \
        _Pragma("unroll")                                                      \
        for (int mt = 0; mt < 2; ++mt)                                         \
            _Pragma("unroll")                                                  \
            for (int nt = 0; nt < 8; ++nt)                                     \
                mma_f16(acc[mt * 8 + nt], af[bi][mt],                          \
                        bf[bi][nt >> 1][nt & 1], bf[bi][nt >> 1][(nt & 1) + 2]);\
    } while (0)

    LOAD_STAGE(0, 0);
    LOAD_STAGE(1, 1);

    uint32_t af[2][2][4], bf[2][4][4];

#pragma unroll
    for (int kt = 0; kt < 8; ++kt) {
        if (kt == 7)
            asm volatile("cp.async.wait_group 0;" ::: "memory");
        else
            asm volatile("cp.async.wait_group 1;" ::: "memory");
        __syncthreads();

        if (kt + 2 < 8) LOAD_STAGE(kt + 2, (kt + 2) % 3);

        const uint32_t sa_  = sb + (kt % 3) * STG;
        const uint32_t sb2_ = sa_ + T_STG;

        LDSM_KS(0, 0, sa_, sb2_);
#pragma unroll
        for (int ks = 0; ks < 4; ++ks) {
            const int cur = ks & 1, nxt = cur ^ 1;
            if (ks < 3) LDSM_KS(ks + 1, nxt, sa_, sb2_);
            MMA_KS(cur);
        }
    }
#undef LOAD_STAGE
#undef LDSM_KS
#undef MMA_KS

    // epilogue
#pragma unroll
    for (int mt = 0; mt < 2; ++mt) {
#pragma unroll
        for (int nt = 0; nt < 8; ++nt) {
            const int m = m0 + wy * 32 + mt * 16 + (lane >> 2);
            const int n = n0 + wx * 64 + nt * 8 + ((lane & 3) << 1);
            const float* a = acc[mt * 8 + nt];
            if (MODE == 0) {
                const int sidx = n >> 9;
                const int h    = (n >> 6) & 7;
                const int d    = n & 63;
                __half* dst = (sidx == 0) ? g_qh : ((sidx == 1) ? g_kh : g_vh);
                const int win = m >> 7;
                const size_t b0i =
                    (((size_t)(win * HEADS + h)) * WIN + (m & 127)) * HD + d;
                const size_t b1i = b0i + 8 * HD;
                *(uint32_t*)&dst[b0i] = packh2(a[0], a[1]);
                *(uint32_t*)&dst[b1i] = packh2(a[2], a[3]);
            } else {
                const float2 bv = *(const float2*)&bias[n];
                *(float2*)&C[(size_t)m * 512 + n] =
                    make_float2(a[0] + bv.x, a[1] + bv.y);
                *(float2*)&C[(size_t)(m + 8) * 512 + n] =
                    make_float2(a[2] + bv.x, a[3] + bv.y);
            }
        }
    }
}

// ---------------------------------------------------------------------------
// HMMA attention, two heads per CTA with pipelined loads:
// CTA = (window, head-pair). QKV(h0) and QKV(h1) are issued as two cp.async
// groups up front; compute(h0) overlaps the in-flight loads of h1.
// Per head: causal block skipping + register softmax + smem-staged coalesced
// O writeback (R15 logic). 110.6 KB smem -> 2 CTAs/SM, 256 threads / 8 warps.
// ---------------------------------------------------------------------------
#define APAD 144                             // bytes per smem row (72 halfs)
#define ATILE (128 * APAD)                   // 18432
#define ABUF  (3 * ATILE)                    // 55296 per head
#define ATTN_SMEM (2 * ABUF)                 // 110592

__global__ void __launch_bounds__(256, 2)
attn_tc()
{
    extern __shared__ __align__(128) char smem[];
    const uint32_t sbase = s2u(smem);

    const int bh2  = blockIdx.x;             // 0..2047
    const int win  = bh2 >> 2;
    const int hp   = bh2 & 3;                // head pair
    const int tid  = threadIdx.x;
    const int warp = tid >> 5, lane = tid & 31;

    // issue both heads' loads up front (group j = QKV of head j)
#pragma unroll
    for (int j = 0; j < 2; ++j) {
        const int bh = win * HEADS + hp * 2 + j;
        const __half* qg = g_qh + (size_t)bh * (WIN * HD);
        const __half* kg = g_kh + (size_t)bh * (WIN * HD);
        const __half* vg = g_vh + (size_t)bh * (WIN * HD);
        const uint32_t sQ = sbase + j * ABUF;
        const uint32_t sK = sQ + ATILE;
        const uint32_t sV = sK + ATILE;
#pragma unroll
        for (int u = 0; u < 4; ++u) {
            const int id  = tid + u * 256;
            const int row = id >> 3, c = id & 7;
            const uint32_t off = row * APAD + c * 16;
            cp16(sQ + off, qg + row * 64 + c * 8);
            cp16(sK + off, kg + row * 64 + c * 8);
            cp16(sV + off, vg + row * 64 + c * 8);
        }
        CP_COMMIT();
    }

    for (int j = 0; j < 2; ++j) {
        if (j == 0)
            asm volatile("cp.async.wait_group 1;" ::: "memory");
        else
            asm volatile("cp.async.wait_group 0;" ::: "memory");
        __syncthreads();

        const uint32_t sQ = sbase + j * ABUF;
        const uint32_t sK = sQ + ATILE;
        const uint32_t sV = sK + ATILE;
        const int bh = win * HEADS + hp * 2 + j;

        // ---- S = Q K^T : per warp 16 x 128; skip np > warp ----
        float sacc[16][4];
#pragma unroll
        for (int i = 0; i < 16; ++i)
#pragma unroll
            for (int jj = 0; jj < 4; ++jj) sacc[i][jj] = 0.0f;

#pragma unroll
        for (int ks = 0; ks < 4; ++ks) {
            const int col = ks * 16 + ((lane >> 4) << 3);
            uint32_t af[4];
            {
                const int row = warp * 16 + (lane & 15);
                ldsm_x4(af, sQ + row * APAD + col * 2);
            }
#pragma unroll
            for (int np = 0; np < 8; ++np) {
                if (np <= warp) {
                    uint32_t bf[4];
                    const int row = np * 16 + (lane & 7) + ((lane >> 3) & 1) * 8;
                    ldsm_x4(bf, sK + row * APAD + col * 2);
                    mma_f16(sacc[np * 2 + 0], af, bf[0], bf[2]);
                    mma_f16(sacc[np * 2 + 1], af, bf[1], bf[3]);
                }
            }
        }

        // ---- causal mask + softmax in registers ----
        const int rlo = warp * 16 + (lane >> 2);
        const int rhi = rlo + 8;
        float mx0 = -1e30f, mx1 = -1e30f;
#pragma unroll
        for (int nt = 0; nt < 16; ++nt) {
            if (nt <= 2 * warp + 1) {
                const int cb = nt * 8 + ((lane & 3) << 1);
                float s0 = sacc[nt][0] * 0.125f;
                float s1 = sacc[nt][1] * 0.125f;
                float s2 = sacc[nt][2] * 0.125f;
                float s3 = sacc[nt][3] * 0.125f;
                if (cb     > rlo) s0 = -1e30f;
                if (cb + 1 > rlo) s1 = -1e30f;
                if (cb     > rhi) s2 = -1e30f;
                if (cb + 1 > rhi) s3 = -1e30f;
                sacc[nt][0] = s0; sacc[nt][1] = s1;
                sacc[nt][2] = s2; sacc[nt][3] = s3;
                mx0 = fmaxf(mx0, fmaxf(s0, s1));
                mx1 = fmaxf(mx1, fmaxf(s2, s3));
            }
        }
        mx0 = fmaxf(mx0, __shfl_xor_sync(0xffffffffu, mx0, 1));
        mx0 = fmaxf(mx0, __shfl_xor_sync(0xffffffffu, mx0, 2));
        mx1 = fmaxf(mx1, __shfl_xor_sync(0xffffffffu, mx1, 1));
        mx1 = fmaxf(mx1, __shfl_xor_sync(0xffffffffu, mx1, 2));

        float sum0 = 0.0f, sum1 = 0.0f;
#pragma unroll
        for (int nt = 0; nt < 16; ++nt) {
            if (nt <= 2 * warp + 1) {
                float e0 = __expf(sacc[nt][0] - mx0);
                float e1 = __expf(sacc[nt][1] - mx0);
                float e2 = __expf(sacc[nt][2] - mx1);
                float e3 = __expf(sacc[nt][3] - mx1);
                sacc[nt][0] = e0; sacc[nt][1] = e1;
                sacc[nt][2] = e2; sacc[nt][3] = e3;
                sum0 += e0 + e1;
                sum1 += e2 + e3;
            }
        }
        sum0 += __shfl_xor_sync(0xffffffffu, sum0, 1);
        sum0 += __shfl_xor_sync(0xffffffffu, sum0, 2);
        sum1 += __shfl_xor_sync(0xffffffffu, sum1, 1);
        sum1 += __shfl_xor_sync(0xffffffffu, sum1, 2);
        const float inv0 = 1.0f / sum0;
        const float inv1 = 1.0f / sum1;

        // ---- O = P V : per warp 16 x 64; skip kt > warp ----
        float oacc[8][4];
#pragma unroll
        for (int i = 0; i < 8; ++i)
#pragma unroll
            for (int jj = 0; jj < 4; ++jj) oacc[i][jj] = 0.0f;

#pragma unroll
        for (int kt = 0; kt < 8; ++kt) {
            if (kt <= warp) {
                uint32_t ap[4];
                ap[0] = packh2(sacc[2 * kt][0] * inv0,     sacc[2 * kt][1] * inv0);
                ap[1] = packh2(sacc[2 * kt][2] * inv1,     sacc[2 * kt][3] * inv1);
                ap[2] = packh2(sacc[2 * kt + 1][0] * inv0, sacc[2 * kt + 1][1] * inv0);
                ap[3] = packh2(sacc[2 * kt + 1][2] * inv1, sacc[2 * kt + 1][3] * inv1);

#pragma unroll
                for (int nb = 0; nb < 4; ++nb) {
                    uint32_t bv[4];
                    const int row = kt * 16 + (lane & 15);
                    const int col = nb * 16 + ((lane >> 4) << 3);
                    ldsm_x4t(bv, sV + row * APAD + col * 2);
                    mma_f16(oacc[nb * 2 + 0], ap, bv[0], bv[1]);
                    mma_f16(oacc[nb * 2 + 1], ap, bv[2], bv[3]);
                }
            }
        }

        // ---- stage O into smem (sV region free after PV) ----
        __syncthreads();
        {
            const uint32_t orow0 = sV + (warp * 16 + (lane >> 2)) * APAD
                                 + ((lane & 3) << 2);
            const uint32_t orow1 = orow0 + 8 * APAD;
#pragma unroll
            for (int nt = 0; nt < 8; ++nt) {
                asm volatile("st.shared.b32 [%0], %1;"
                    :: "r"(orow0 + nt * 16), "r"(packh2(oacc[nt][0], oacc[nt][1]))
                    : "memory");
                asm volatile("st.shared.b32 [%0], %1;"
                    :: "r"(orow1 + nt * 16), "r"(packh2(oacc[nt][2], oacc[nt][3]))
                    : "memory");
            }
        }
        __syncthreads();

        // ---- coalesced flush ----
        const int h = bh & 7;
#pragma unroll
        for (int u = 0; u < 4; ++u) {
            const int id  = tid + u * 256;
            const int row = id >> 3, c = id & 7;
            uint4 v;
            asm volatile("ld.shared.v4.b32 {%0,%1,%2,%3}, [%4];"
                : "=r"(v.x), "=r"(v.y), "=r"(v.z), "=r"(v.w)
                : "r"(sV + row * APAD + c * 16));
            *(uint4*)&g_oh[(size_t)(win * WIN + row) * DIMC + h * HD + c * 8] = v;
        }
    }
}

// ---------------------------------------------------------------------------
extern "C" void kernel_launch(void* const* d_in, const int* in_sizes, int n_in,
                              void* d_out, int out_size)
{
    const float* x      = (const float*)d_in[0];  // [16,4096,512]
    const float* w_qkv  = (const float*)d_in[1];  // [1536,512]
    const float* w_proj = (const float*)d_in[2];  // [512,512]
    const float* b_proj = (const float*)d_in[3];  // [512]
    float* out = (float*)d_out;                   // [16,4096,512]

    cudaFuncSetAttribute(hgemm<0>, cudaFuncAttributeMaxDynamicSharedMemorySize,
                         GEMM_SMEM);
    cudaFuncSetAttribute(hgemm<1>, cudaFuncAttributeMaxDynamicSharedMemorySize,
                         GEMM_SMEM);
    cudaFuncSetAttribute(hgemm<0>,
                         cudaFuncAttributePreferredSharedMemoryCarveout, 100);
    cudaFuncSetAttribute(hgemm<1>,
                         cudaFuncAttributePreferredSharedMemoryCarveout, 100);
    cudaFuncSetAttribute(attn_tc, cudaFuncAttributeMaxDynamicSharedMemorySize,
                         ATTN_SMEM);
    cudaFuncSetAttribute(attn_tc,
                         cudaFuncAttributePreferredSharedMemoryCarveout, 100);

    // 0) fp32 -> fp16 conversions (single launch)
    cvt_all<<<(N4_ALL + 255) / 256, 256>>>(x, w_qkv, w_proj);

    // 1) fused QKV projection -> fp16 g_qh/g_kh/g_vh
    dim3 g1(1536 / 128, NTOK / 128);
    hgemm<0><<<g1, 256, GEMM_SMEM>>>(nullptr, nullptr);

    // 2) HMMA attention (2 heads/CTA, pipelined loads) -> fp16 g_oh
    attn_tc<<<BH / 2, 256, ATTN_SMEM>>>();

    // 3) output projection + bias -> fp32 d_out
    dim3 g2(512 / 128, NTOK / 128);
    hgemm<1><<<g2, 256, GEMM_SMEM>>>(out, b_proj);
}